// round 17
// baseline (speedup 1.0000x reference)
#include <cuda_runtime.h>
#include <cuda_fp16.h>
#include <cuda_bf16.h>
#include <math.h>
#include <stdint.h>

#define NPOS 16384          // H*W
#define NB   16             // batch
#define NCH  128            // C == hidden
#define NTILE (NB * NPOS / 64)   // 4096 64-row q tiles
#define NBLK  (NB * NPOS / 128)  // 2048 k_qkv blocks (128 pos each)

// ---------------- device scratch (allocation-free rule: __device__ globals) ----
__device__ uint32_t g_q    [NTILE * 4096];  // q fp16 pairs, swizzled 64x128 tiles
__device__ uint32_t g_part [NBLK * 2176];   // per 128-pos block: 2048 bf16x2 ctx + 128 f32 se
__device__ uint32_t g_W2   [NB * 8192];     // fused W2 fp16, swizzled 128x128 per b
__device__ uint32_t g_wsw  [3 * 8192];      // w_qkv fp16, 3 swizzled 128x128 chunks

// ---------------- helpers -------------------------------------------------------
__device__ __forceinline__ uint32_t smem_u32(const void* p) {
    uint32_t a;
    asm("{ .reg .u64 t; cvta.to.shared.u64 t, %1; cvt.u32.u64 %0, t; }" : "=r"(a) : "l"(p));
    return a;
}
// swizzled byte offset within a 128-col b16 tile (256B rows)
__device__ __forceinline__ uint32_t toff(int r, int c) {
    return (uint32_t)(r * 256 + (((c >> 3) ^ (r & 7)) << 4) + ((c & 7) << 1));
}
__device__ __forceinline__ void ldsm4(uint32_t* r, uint32_t a) {
    asm volatile("ldmatrix.sync.aligned.m8n8.x4.shared.b16 {%0,%1,%2,%3}, [%4];"
                 : "=r"(r[0]), "=r"(r[1]), "=r"(r[2]), "=r"(r[3]) : "r"(a));
}
__device__ __forceinline__ void ldsm4t(uint32_t* r, uint32_t a) {
    asm volatile("ldmatrix.sync.aligned.m8n8.x4.trans.shared.b16 {%0,%1,%2,%3}, [%4];"
                 : "=r"(r[0]), "=r"(r[1]), "=r"(r[2]), "=r"(r[3]) : "r"(a));
}
__device__ __forceinline__ void mma16816(float* d, const uint32_t* a, uint32_t b0, uint32_t b1) {
    asm volatile(
        "mma.sync.aligned.m16n8k16.row.col.f32.f16.f16.f32 "
        "{%0,%1,%2,%3}, {%4,%5,%6,%7}, {%8,%9}, {%0,%1,%2,%3};"
        : "+f"(d[0]), "+f"(d[1]), "+f"(d[2]), "+f"(d[3])
        : "r"(a[0]), "r"(a[1]), "r"(a[2]), "r"(a[3]), "r"(b0), "r"(b1));
}
__device__ __forceinline__ uint32_t pack_h2(float a, float b) {
    __half2 h = __floats2half2_rn(a, b);
    return *(uint32_t*)&h;
}
__device__ __forceinline__ void cp_async16(uint32_t smem_dst, const void* gsrc) {
    asm volatile("cp.async.cg.shared.global [%0], [%1], 16;" :: "r"(smem_dst), "l"(gsrc));
}

// =============================================================================
// K0: convert w_qkv to fp16, pre-swizzled, 3 chunks of 128x128
// =============================================================================
__global__ __launch_bounds__(256)
void k_prep(const float* __restrict__ w_qkv)
{
    int idx = blockIdx.x * 256 + threadIdx.x;   // 24576 items
    int chunk = idx >> 13, rem = idx & 8191;
    int o = rem >> 6, cp = rem & 63;
    int c0 = cp * 2;
    float v0 = w_qkv[(size_t)(chunk * 128 + o) * NCH + c0];
    float v1 = w_qkv[(size_t)(chunk * 128 + o) * NCH + c0 + 1];
    g_wsw[(uint32_t)chunk * 8192 + (toff(o, c0) >> 2)] = pack_h2(v0, v1);
}

// =============================================================================
// K1: fused qkv-GEMM (fp16) + q-softmax + ctx partial, 128 positions/block.
// grid 2048, 2 CTAs/SM.  cp.async prefetch of next w chunk.  q staged in EK
// smem during chunk 0, then copied out coalesced.
// smem: X 32K (x -> v) | W 32K (w chunk -> ctx red staging) | EK 32K (q -> ek)
//       | SE 2K  = 100,352 B
// =============================================================================
#define Q_X   0
#define Q_W   32768
#define Q_EK  65536
#define Q_SE  98304
#define Q_SMEM 100352

__global__ __launch_bounds__(256, 2)
void k_qkv(const float* __restrict__ x)
{
    extern __shared__ char smc[];
    const uint32_t sb = smem_u32(smc);
    const int tid = threadIdx.x;
    const int warp = tid >> 5, lane = tid & 31;
    const int wm = warp & 3, wn = warp >> 2;        // wm: 4x32 pos, wn: 2x64 ch

    const int b    = blockIdx.x >> 7;
    const int tile = blockIdx.x & 127;
    const int n0   = tile << 7;

    // ---- load x tile [c=128][p=128] as fp16, toff swizzle; w chunk0 copy ----
    {
        const float* xb = x + (size_t)b * NCH * NPOS + n0;
#pragma unroll
        for (int i = 0; i < 16; i++) {
            int lin = tid + i * 256;            // 4096 float4
            int c = lin >> 5, pq = lin & 31;
            float4 v = *(const float4*)(xb + (size_t)c * NPOS + pq * 4);
            uint32_t o = toff(c, pq * 4);
            *(uint32_t*)(smc + Q_X + o)     = pack_h2(v.x, v.y);
            *(uint32_t*)(smc + Q_X + o + 4) = pack_h2(v.z, v.w);
        }
#pragma unroll
        for (int i = 0; i < 8; i++) {
            int lin = tid + i * 256;            // 2048 uint4
            ((uint4*)(smc + Q_W))[lin] = ((const uint4*)g_wsw)[lin];
        }
    }
    __syncthreads();

    const int l7 = lane & 7, lb3 = (lane >> 3) & 1, lb4 = (lane >> 4) & 1;
    const float scale = 0.17677669529663687f;   // 32^-0.5

    for (int chunk = 0; chunk < 3; chunk++) {
        float acc[2][8][4];
#pragma unroll
        for (int mt = 0; mt < 2; mt++)
#pragma unroll
            for (int u = 0; u < 8; u++)
#pragma unroll
                for (int r = 0; r < 4; r++) acc[mt][u][r] = 0.f;

        // single fp16 pass: warp computes 32 pos x 64 ch
#pragma unroll
        for (int k = 0; k < 8; k++) {
            uint32_t a[2][4];
#pragma unroll
            for (int mt = 0; mt < 2; mt++)
                ldsm4t(a[mt], sb + Q_X + toff(k * 16 + l7 + lb4 * 8, wm * 32 + mt * 16 + lb3 * 8));
            uint32_t bf[4][4];
#pragma unroll
            for (int u2 = 0; u2 < 4; u2++)
                ldsm4(bf[u2], sb + Q_W + toff(wn * 64 + u2 * 16 + l7 + lb4 * 8, k * 16 + lb3 * 8));
#pragma unroll
            for (int mt = 0; mt < 2; mt++)
#pragma unroll
                for (int u = 0; u < 8; u++)
                    mma16816(acc[mt][u], a[mt], bf[u >> 1][(u & 1) * 2],
                             bf[u >> 1][(u & 1) * 2 + 1]);
        }
        __syncthreads();   // all MMA reads of Q_W (and Q_X for chunk 2) complete

        // prefetch next w chunk into Q_W, overlapped with the epilogue below
        if (chunk < 2) {
#pragma unroll
            for (int i = 0; i < 8; i++) {
                int lin = tid + i * 256;
                cp_async16(sb + Q_W + lin * 16, ((const uint4*)g_wsw) + (chunk + 1) * 2048 + lin);
            }
            asm volatile("cp.async.commit_group;");
        }

        // ---- epilogues (warp owns 32 pos x 64 ch = 2 heads) ----
        if (chunk == 0) {
            // q softmax -> EK smem tile (coalesced copy-out after the barrier)
#pragma unroll
            for (int mt = 0; mt < 2; mt++)
#pragma unroll
            for (int h8 = 0; h8 < 2; h8++) {
                float e[8][2];
                float sA = 0.f, sB = 0.f;
#pragma unroll
                for (int u = 0; u < 8; u++)
#pragma unroll
                    for (int j = 0; j < 2; j++) {
                        float v = __expf(acc[mt][u][h8 * 2 + j]);
                        e[u][j] = v;
                        if (u < 4) sA += v; else sB += v;
                    }
                sA += __shfl_xor_sync(0xffffffffu, sA, 1);
                sA += __shfl_xor_sync(0xffffffffu, sA, 2);
                sB += __shfl_xor_sync(0xffffffffu, sB, 1);
                sB += __shfl_xor_sync(0xffffffffu, sB, 2);
                const float invA = scale / sA, invB = scale / sB;
                const int p = wm * 32 + mt * 16 + h8 * 8 + (lane >> 2);
#pragma unroll
                for (int u = 0; u < 8; u++) {
                    float inv = (u < 4) ? invA : invB;
                    int ch0 = wn * 64 + u * 8 + (lane & 3) * 2;
                    *(uint32_t*)(smc + Q_EK + toff(p, ch0)) = pack_h2(e[u][0] * inv, e[u][1] * inv);
                }
            }
        } else if (chunk == 1) {
            // ek = exp(k): fp16 into EK; sumexp partials (f32 exact)
            float sep[8][2];
#pragma unroll
            for (int u = 0; u < 8; u++) { sep[u][0] = 0.f; sep[u][1] = 0.f; }
#pragma unroll
            for (int mt = 0; mt < 2; mt++)
#pragma unroll
            for (int h8 = 0; h8 < 2; h8++) {
                const int p = wm * 32 + mt * 16 + h8 * 8 + (lane >> 2);
#pragma unroll
                for (int u = 0; u < 8; u++) {
                    float v0 = __expf(acc[mt][u][h8 * 2]);
                    float v1 = __expf(acc[mt][u][h8 * 2 + 1]);
                    sep[u][0] += v0; sep[u][1] += v1;
                    int ch0 = wn * 64 + u * 8 + (lane & 3) * 2;
                    *(uint32_t*)(smc + Q_EK + toff(p, ch0)) = pack_h2(v0, v1);
                }
            }
            float* se = (float*)(smc + Q_SE);   // [8 warps][64]
#pragma unroll
            for (int u = 0; u < 8; u++)
#pragma unroll
                for (int j = 0; j < 2; j++) {
                    float s = sep[u][j];
                    s += __shfl_xor_sync(0xffffffffu, s, 4);
                    s += __shfl_xor_sync(0xffffffffu, s, 8);
                    s += __shfl_xor_sync(0xffffffffu, s, 16);
                    if ((lane >> 2) == 0)
                        se[warp * 64 + u * 8 + (lane & 3) * 2 + j] = s;
                }
        } else {
            // v: fp16 -> X (x reads finished at the post-MMA barrier)
#pragma unroll
            for (int mt = 0; mt < 2; mt++)
#pragma unroll
            for (int h8 = 0; h8 < 2; h8++) {
                const int p = wm * 32 + mt * 16 + h8 * 8 + (lane >> 2);
#pragma unroll
                for (int u = 0; u < 8; u++) {
                    int ch0 = wn * 64 + u * 8 + (lane & 3) * 2;
                    *(uint32_t*)(smc + Q_X + toff(p, ch0)) =
                        pack_h2(acc[mt][u][h8 * 2], acc[mt][u][h8 * 2 + 1]);
                }
            }
        }

        if (chunk < 2) asm volatile("cp.async.wait_group 0;" ::: "memory");
        __syncthreads();

        // coalesced q copy-out (EK holds the q tile; completes before chunk-1's
        // epilogue rewrites EK, guaranteed by chunk-1's post-MMA barrier)
        if (chunk == 0) {
            const uint4* src = (const uint4*)(smc + Q_EK);
            uint4* dstg = (uint4*)g_q + (size_t)blockIdx.x * 2048;
#pragma unroll
            for (int i = 0; i < 8; i++) {
                int lin = tid + i * 256;        // 2048 uint4; 16 per 256B row
                int p = lin >> 4;
                dstg[(p >> 6) * 1024 + (p & 63) * 16 + (lin & 15)] = src[lin];
            }
        }
    }

    // ---- ctx partial: ctx_h[d][e] = sum_{p<128} ek[p,d] v[p,e] ----
    const int h = warp & 3, ks = warp >> 2;   // ks: 2 slices of 64 p
    float ctx[2][4][4];
#pragma unroll
    for (int mt = 0; mt < 2; mt++)
#pragma unroll
        for (int u = 0; u < 4; u++)
#pragma unroll
            for (int r = 0; r < 4; r++) ctx[mt][u][r] = 0.f;

#pragma unroll
    for (int kk = 0; kk < 4; kk++) {
        const int p0 = ks * 64 + kk * 16;
        uint32_t a[2][4];
#pragma unroll
        for (int mt = 0; mt < 2; mt++)
            ldsm4t(a[mt], sb + Q_EK + toff(p0 + l7 + lb4 * 8, h * 32 + mt * 16 + lb3 * 8));
        uint32_t bfr[2][4];
#pragma unroll
        for (int nt = 0; nt < 2; nt++)
            ldsm4t(bfr[nt], sb + Q_X + toff(p0 + l7 + lb3 * 8, h * 32 + nt * 16 + lb4 * 8));
#pragma unroll
        for (int mt = 0; mt < 2; mt++)
#pragma unroll
            for (int u = 0; u < 4; u++)
                mma16816(ctx[mt][u], a[mt], bfr[u >> 1][(u & 1) * 2],
                         bfr[u >> 1][(u & 1) * 2 + 1]);
    }

    // two-phase ctx staging into 16KB red buffer (aliases Q_W)
    float* rb = (float*)(smc + Q_W);
    __syncthreads();
    if (ks == 0) {
#pragma unroll
        for (int mt = 0; mt < 2; mt++)
#pragma unroll
            for (int u = 0; u < 4; u++) {
                int dr = mt * 16 + (lane >> 2), e = u * 8 + (lane & 3) * 2;
                float* r = rb + h * 1024;
                r[dr * 32 + e]           = ctx[mt][u][0];
                r[dr * 32 + e + 1]       = ctx[mt][u][1];
                r[(dr + 8) * 32 + e]     = ctx[mt][u][2];
                r[(dr + 8) * 32 + e + 1] = ctx[mt][u][3];
            }
    }
    __syncthreads();
    if (ks == 1) {
#pragma unroll
        for (int mt = 0; mt < 2; mt++)
#pragma unroll
            for (int u = 0; u < 4; u++) {
                int dr = mt * 16 + (lane >> 2), e = u * 8 + (lane & 3) * 2;
                float* r = rb + h * 1024;
                r[dr * 32 + e]           += ctx[mt][u][0];
                r[dr * 32 + e + 1]       += ctx[mt][u][1];
                r[(dr + 8) * 32 + e]     += ctx[mt][u][2];
                r[(dr + 8) * 32 + e + 1] += ctx[mt][u][3];
            }
    }
    __syncthreads();

    // ---- write block partial: 2048 bf16x2 ctx + 128 f32 se ----
    {
        const size_t pbase = (size_t)blockIdx.x * 2176;
#pragma unroll
        for (int i = 0; i < 8; i++) {
            int idx = tid + i * 256;            // 2048
            __nv_bfloat162 pkt = __float22bfloat162_rn(make_float2(rb[idx * 2], rb[idx * 2 + 1]));
            g_part[pbase + idx] = *(uint32_t*)&pkt;
        }
        if (tid < 128) {
            const float* se = (const float*)(smc + Q_SE);
            int wq = tid >> 6, c64 = tid & 63;   // ch = wq*64 + c64
            float s = se[(wq * 4 + 0) * 64 + c64] + se[(wq * 4 + 1) * 64 + c64]
                    + se[(wq * 4 + 2) * 64 + c64] + se[(wq * 4 + 3) * 64 + c64];
            g_part[pbase + 2048 + tid] = __float_as_uint(s);
        }
    }
}

// =============================================================================
// K2: fused reduce(128 tile partials) + normalize + build W2 (fp16).
// grid = NB (one block per batch), 512 threads.
// smem: ctxs 4224 f32 | Ss 128 f32 | ws2 16384 f32 = 82,944 B
// =============================================================================
#define W2_SMEM 82944

__global__ __launch_bounds__(512, 1)
void k_w2(const float* __restrict__ w_out)
{
    extern __shared__ float sm[];
    float* ctxs = sm;            // [h][d][33]
    float* Ss   = sm + 4224;
    float* ws2  = sm + 4352;     // [c][ch] full w_out copy

    const int b = blockIdx.x;
    const int tid = threadIdx.x;
    const uint32_t* pb = g_part + (size_t)b * 128 * 2176;

    // full w_out copy (coalesced)
    for (int lin = tid; lin < 16384; lin += 512)
        ws2[lin] = w_out[lin];

    // reduce 128 tile partials
#pragma unroll
    for (int it = 0; it < 5; it++) {
        int col = tid + it * 512;           // 0..2175 (last iter partial)
        if (col >= 2176) break;
        const uint32_t* src = pb + col;
        if (col < 2048) {
            float s0 = 0.f, s1 = 0.f;
#pragma unroll 8
            for (int t = 0; t < 128; t++) {
                uint32_t u = src[(size_t)t * 2176];
                float2 f = __bfloat1622float2(*(__nv_bfloat162*)&u);
                s0 += f.x; s1 += f.y;
            }
            int idx = col * 2;
            int h0 = idx >> 10, de0 = idx & 1023;
            ctxs[h0 * 1056 + (de0 >> 5) * 33 + (de0 & 31)] = s0;
            int idx1 = idx + 1;
            int h1 = idx1 >> 10, de1 = idx1 & 1023;
            ctxs[h1 * 1056 + (de1 >> 5) * 33 + (de1 & 31)] = s1;
        } else {
            float s = 0.f;
#pragma unroll 8
            for (int t = 0; t < 128; t++)
                s += __uint_as_float(src[(size_t)t * 2176]);
            Ss[col - 2048] = 1.0f / s;
        }
    }
    __syncthreads();

    // build W2: 8192 fp16-pair outputs, 16 iterations
    for (int oidx = tid; oidx < 8192; oidx += 512) {
        int cl = oidx >> 6, cpp = oidx & 63;
        int ch0 = cpp * 2;
        int h = ch0 >> 5, d = ch0 & 31;
        const float* cr0 = &ctxs[h * 1056 + d * 33];
        const float* cr1 = cr0 + 33;
        const float* wr  = &ws2[cl * 128 + h * 32];
        float a0 = 0.f, a1 = 0.f;
#pragma unroll
        for (int e = 0; e < 32; e++) {
            a0 = fmaf(wr[e], cr0[e], a0);
            a1 = fmaf(wr[e], cr1[e], a1);
        }
        g_W2[(uint32_t)b * 8192 + (toff(cl, ch0) >> 2)] =
            pack_h2(a0 * Ss[ch0], a1 * Ss[ch0 + 1]);
    }
}

// =============================================================================
// K3: y = W2_b @ q + b_out via fp16 mma, LayerNorm fused.  2 q-tiles per block
// (W2 loaded once), grid 2048, 3 CTAs/SM.  smem ~68 KB.
// =============================================================================
#define K3_W   0
#define K3_Q0  32768
#define K3_RS  65536
#define K3_RQ  66560
#define K3_MU  67584
#define K3_RST 67840
#define K3_SMEM 68096

__global__ __launch_bounds__(256, 3)
void k_out(const float* __restrict__ b_out, const float* __restrict__ ln_g,
           const float* __restrict__ ln_b, float* __restrict__ out)
{
    extern __shared__ char smc[];
    const uint32_t sb = smem_u32(smc);
    float* red_s = (float*)(smc + K3_RS);    // [4][64]
    float* red_q = (float*)(smc + K3_RQ);    // [4][64]
    float* mu_s  = (float*)(smc + K3_MU);    // [64]
    float* rs_s  = (float*)(smc + K3_RST);   // [64]

    const int tid = threadIdx.x;
    const int warp = tid >> 5, lane = tid & 31;
    const int wm = warp & 3, wn = warp >> 2;          // wn in {0,1}
    const int b  = blockIdx.x >> 7;
    const int tp = blockIdx.x & 127;                  // tile pair
    const size_t qt0 = ((size_t)b * 256 + tp * 2) * 1024;   // uint4 base, tile 0

#pragma unroll
    for (int i = 0; i < 8; i++) {
        int lin = tid + i * 256;              // 2048 uint4: W2 tile
        ((uint4*)(smc + K3_W))[lin] = ((const uint4*)g_W2)[(size_t)b * 2048 + lin];
    }
#pragma unroll
    for (int i = 0; i < 8; i++) {
        int lin = tid + i * 256;              // 2048 uint4: two q tiles
        ((uint4*)(smc + K3_Q0))[lin] = ((const uint4*)g_q)[qt0 + lin];
    }
    __syncthreads();

    const int l7 = lane & 7, lb3 = (lane >> 3) & 1, lb4 = (lane >> 4) & 1;

    for (int t2 = 0; t2 < 2; t2++) {
        const int n0 = (tp * 2 + t2) << 6;
        const uint32_t qB = sb + K3_Q0 + t2 * 16384;

        float acc[2][4][4];
#pragma unroll
        for (int mt = 0; mt < 2; mt++)
#pragma unroll
            for (int u = 0; u < 4; u++)
#pragma unroll
                for (int r = 0; r < 4; r++) acc[mt][u][r] = 0.f;

#pragma unroll
        for (int k = 0; k < 8; k++) {
            uint32_t a[2][4];
#pragma unroll
            for (int mt = 0; mt < 2; mt++)
                ldsm4(a[mt], sb + K3_W + toff(wm * 32 + mt * 16 + l7 + lb3 * 8, k * 16 + lb4 * 8));
            uint32_t bfr[2][4];
#pragma unroll
            for (int nt = 0; nt < 2; nt++)
                ldsm4(bfr[nt], qB + toff(wn * 32 + nt * 16 + l7 + lb4 * 8, k * 16 + lb3 * 8));
#pragma unroll
            for (int mt = 0; mt < 2; mt++)
#pragma unroll
                for (int u = 0; u < 4; u++)
                    mma16816(acc[mt][u], a[mt], bfr[u >> 1][(u & 1) * 2], bfr[u >> 1][(u & 1) * 2 + 1]);
        }

        // bias
#pragma unroll
        for (int mt = 0; mt < 2; mt++)
#pragma unroll
            for (int h8 = 0; h8 < 2; h8++) {
                const float bo = b_out[wm * 32 + mt * 16 + h8 * 8 + (lane >> 2)];
#pragma unroll
                for (int u = 0; u < 4; u++) {
                    acc[mt][u][h8 * 2]     += bo;
                    acc[mt][u][h8 * 2 + 1] += bo;
                }
            }

        // LN partials
#pragma unroll
        for (int u = 0; u < 4; u++)
#pragma unroll
            for (int j = 0; j < 2; j++) {
                float a0 = acc[0][u][j],     a1 = acc[0][u][2 + j];
                float a2 = acc[1][u][j],     a3 = acc[1][u][2 + j];
                float s = a0 + a1 + a2 + a3;
                float q = a0 * a0 + a1 * a1 + a2 * a2 + a3 * a3;
                s += __shfl_xor_sync(0xffffffffu, s, 4);
                q += __shfl_xor_sync(0xffffffffu, q, 4);
                s += __shfl_xor_sync(0xffffffffu, s, 8);
                q += __shfl_xor_sync(0xffffffffu, q, 8);
                s += __shfl_xor_sync(0xffffffffu, s, 16);
                q += __shfl_xor_sync(0xffffffffu, q, 16);
                if ((lane >> 2) == 0) {
                    int col = wn * 32 + u * 8 + (lane & 3) * 2 + j;
                    red_s[wm * 64 + col] = s;
                    red_q[wm * 64 + col] = q;
                }
            }
        __syncthreads();

        if (tid < 64) {
            float s = red_s[tid] + red_s[64 + tid] + red_s[128 + tid] + red_s[192 + tid];
            float q = red_q[tid] + red_q[64 + tid] + red_q[128 + tid] + red_q[192 + tid];
            float mu  = s * (1.0f / 128.0f);
            float var = q * (1.0f / 128.0f) - mu * mu;
            mu_s[tid] = mu;
            rs_s[tid] = rsqrtf(var + 1e-5f);
        }
        __syncthreads();

#pragma unroll
        for (int mt = 0; mt < 2; mt++)
#pragma unroll
            for (int h8 = 0; h8 < 2; h8++) {
                const int c = wm * 32 + mt * 16 + h8 * 8 + (lane >> 2);
                const float g  = ln_g[c];
                const float bb = ln_b[c];
                float* rowp = out + ((size_t)b * NCH + c) * NPOS + n0 + wn * 32 + (lane & 3) * 2;
#pragma unroll
                for (int u = 0; u < 4; u++) {
                    int col = wn * 32 + u * 8 + (lane & 3) * 2;
                    float v0 = (acc[mt][u][h8 * 2]     - mu_s[col])     * rs_s[col]     * g + bb;
                    float v1 = (acc[mt][u][h8 * 2 + 1] - mu_s[col + 1]) * rs_s[col + 1] * g + bb;
                    *(float2*)(rowp + u * 8) = make_float2(v0, v1);
                }
            }
        __syncthreads();   // red/mu buffers reused by next tile
    }
}

// =============================================================================
extern "C" void kernel_launch(void* const* d_in, const int* in_sizes, int n_in,
                              void* d_out, int out_size)
{
    const float* x     = (const float*)d_in[0];
    const float* w_qkv = (const float*)d_in[1];
    const float* w_out = (const float*)d_in[2];
    const float* b_out = (const float*)d_in[3];
    const float* ln_g  = (const float*)d_in[4];
    const float* ln_b  = (const float*)d_in[5];
    float* out = (float*)d_out;

    cudaFuncSetAttribute(k_qkv, cudaFuncAttributeMaxDynamicSharedMemorySize, Q_SMEM);
    cudaFuncSetAttribute(k_w2,  cudaFuncAttributeMaxDynamicSharedMemorySize, W2_SMEM);
    cudaFuncSetAttribute(k_out, cudaFuncAttributeMaxDynamicSharedMemorySize, K3_SMEM);

    k_prep<<<96, 256>>>(w_qkv);
    k_qkv<<<2048, 256, Q_SMEM>>>(x);
    k_w2<<<16, 512, W2_SMEM>>>(w_out);
    k_out<<<2048, 256, K3_SMEM>>>(b_out, ln_g, ln_b, out);
}